// round 6
// baseline (speedup 1.0000x reference)
#include <cuda_runtime.h>
#include <math.h>
#include <float.h>

// Fixed problem shape: img (16,3,512,512) f32, sbin=4 -> out (16,31,128,128) f32
#define BATCH 16
#define NCH   3
#define IH    512
#define IW    512
#define BH    128
#define BW    128

#define PPITCH 520          // padded u32 pitch: 4 zero cols + 512 px + 4 zero cols
#define HIST_ELEMS (BATCH * 18 * BH * BW)
#define NORM_ELEMS (BATCH * BH * BW)

__device__ unsigned int g_pack[BATCH * IH * PPITCH];   // mag|bo packed, 17 MB
__device__ float g_hist[HIST_ELEMS];
__device__ float g_norm[NORM_ELEMS];

// ---------------------------------------------------------------------------
// K1: gradient + orientation per pixel, each pixel computed exactly once.
// Output: g_pack[b][y][4 + x] = (magbits & ~31) | bo   (zeros on borders/pads)
// ---------------------------------------------------------------------------
__global__ __launch_bounds__(256) void hog_grad(const float* __restrict__ img) {
    const int t  = blockIdx.x * 256 + threadIdx.x;   // strip id
    const int sx = t & 127;            // 4-px strip index within row
    const int yy = (t >> 7) & 511;     // image row
    const int b  = t >> 16;            // batch
    const int xb = sx * 4;

    const float UU[9] = {1.0f, 0.9397f, 0.766f, 0.5f, 0.1736f,
                         -0.1736f, -0.5f, -0.766f, -0.9397f};
    const float VV[9] = {0.0f, 0.342f, 0.6428f, 0.866f, 0.9848f,
                         0.9848f, 0.866f, 0.6428f, 0.342f};

    unsigned int pk[4] = {0u, 0u, 0u, 0u};

    if (yy >= 1 && yy <= IH - 2) {
        const float* base = img + (size_t)b * NCH * IH * IW;

        float v0[4], v1[4], v2[4];          // grad energy per channel
        float dxc[3][4], dyc[3][4];
#pragma unroll
        for (int c = 0; c < NCH; c++) {
            const float* rp = base + (size_t)c * IH * IW + (size_t)yy * IW + xb;
            float4 up = *reinterpret_cast<const float4*>(rp - IW);
            float4 dn = *reinterpret_cast<const float4*>(rp + IW);
            float4 md = *reinterpret_cast<const float4*>(rp);
            float  lf = (sx > 0)   ? rp[-1] : 0.f;
            float  rt = (sx < 127) ? rp[4]  : 0.f;
            float mx[6] = {lf, md.x, md.y, md.z, md.w, rt};
            float u[4]  = {up.x, up.y, up.z, up.w};
            float d[4]  = {dn.x, dn.y, dn.z, dn.w};
            float* vv = (c == 0) ? v0 : (c == 1) ? v1 : v2;
#pragma unroll
            for (int i = 0; i < 4; i++) {
                float gdy = d[i] - u[i];
                float gdx = mx[i + 2] - mx[i];
                dxc[c][i] = gdx;
                dyc[c][i] = gdy;
                vv[i] = gdx * gdx + gdy * gdy;
            }
        }

#pragma unroll
        for (int i = 0; i < 4; i++) {
            // channel argmax (first occurrence wins ties)
            float vm = fmaxf(v0[i], fmaxf(v1[i], v2[i]));
            float gdx, gdy;
            if (vm == v0[i])      { gdx = dxc[0][i]; gdy = dyc[0][i]; }
            else if (vm == v1[i]) { gdx = dxc[1][i]; gdy = dyc[1][i]; }
            else                  { gdx = dxc[2][i]; gdy = dyc[2][i]; }

            float maxv = -FLT_MAX, minv = FLT_MAX;
            int   maxi = 0,        mini = 0;
#pragma unroll
            for (int k = 0; k < 9; k++) {
                float dd = UU[k] * gdx + VV[k] * gdy;
                if (dd > maxv) { maxv = dd; maxi = k; }
                if (dd < minv) { minv = dd; mini = k; }
            }
            int bo = (maxv >= -minv) ? maxi : mini + 9;
            float mag = (vm > 0.f) ? vm * rsqrtf(vm) : 0.f;
            int x = xb + i;
            if (x < 1 || x > IW - 2) mag = 0.f;
            pk[i] = (__float_as_uint(mag) & 0xFFFFFFE0u) | (unsigned)bo;
        }
    }

    unsigned int* row = g_pack + ((size_t)b * IH + yy) * PPITCH;
    *reinterpret_cast<uint4*>(row + 4 + xb) = make_uint4(pk[0], pk[1], pk[2], pk[3]);
    if (sx == 0)
        *reinterpret_cast<uint4*>(row) = make_uint4(0u, 0u, 0u, 0u);
    if (sx == 127)
        *reinterpret_cast<uint4*>(row + 516) = make_uint4(0u, 0u, 0u, 0u);
}

// ---------------------------------------------------------------------------
// K2: per-cell 8x8 gather from g_pack + cell norm. 1 thread = 1 cell.
// No __syncthreads needed (bins are thread-private in smem).
// ---------------------------------------------------------------------------
__global__ __launch_bounds__(256) void hog_cell() {
    __shared__ float s_bins[18 * 256];   // 18432 B

    const int tid = threadIdx.x;
    const int cx  = blockIdx.x * 16 + (tid & 15);
    const int cy  = blockIdx.y * 16 + (tid >> 4);
    const int b   = blockIdx.z;

#pragma unroll
    for (int o = 0; o < 18; o++) s_bins[o * 256 + tid] = 0.0f;

    const float W8[8] = {0.125f, 0.375f, 0.625f, 0.875f,
                         0.875f, 0.625f, 0.375f, 0.125f};

#pragma unroll
    for (int dy = 0; dy < 8; dy++) {
        const int y = 4 * cy - 2 + dy;
        if (y < 0 || y > IH - 1) continue;   // only cy==0 / cy==127 rows
        const uint4* rp = reinterpret_cast<const uint4*>(
            g_pack + ((size_t)b * IH + y) * PPITCH + 4 * cx);
        uint4 p0 = rp[0];
        uint4 p1 = rp[1];
        uint4 p2 = rp[2];
        // pixels px = 4*cx-2+dx live at buffer cols 4*cx+2 .. 4*cx+9 = v[2..9]
        unsigned int v[12] = {p0.x, p0.y, p0.z, p0.w,
                              p1.x, p1.y, p1.z, p1.w,
                              p2.x, p2.y, p2.z, p2.w};
        const float wy = W8[dy];
#pragma unroll
        for (int dx = 0; dx < 8; dx++) {
            unsigned int u = v[dx + 2];
            float m = __uint_as_float(u & 0xFFFFFFE0u);
            int o = (int)(u & 31u);
            s_bins[o * 256 + tid] += m * (wy * W8[dx]);
        }
    }

    // write hist (plane layout, coalesced) + norm
    float* hb = g_hist + ((size_t)b * 18) * (BH * BW) + cy * BW + cx;
    float acc = 0.0f;
#pragma unroll
    for (int o = 0; o < 9; o++) {
        float a = s_bins[o * 256 + tid];
        float c = s_bins[(o + 9) * 256 + tid];
        hb[o * (BH * BW)]       = a;
        hb[(o + 9) * (BH * BW)] = c;
        float s = a + c;
        acc += s * s;
    }
    g_norm[(size_t)b * BH * BW + cy * BW + cx] = acc;
}

// ---------------------------------------------------------------------------
// K3: block-normalized features (31 channels), 1 px/thread
// ---------------------------------------------------------------------------
__global__ void hog_feat(float* __restrict__ out) {
    int idx = blockIdx.x * blockDim.x + threadIdx.x;
    if (idx >= BATCH * BH * BW) return;
    int j = idx & (BW - 1);
    int t = idx >> 7;
    int i = t & (BH - 1);
    int b = t >> 7;

    float* ob = out + (size_t)b * 31 * BH * BW + i * BW + j;

    if (i == 0 || i == BH - 1 || j == 0 || j == BW - 1) {
#pragma unroll
        for (int ch = 0; ch < 31; ch++) ob[ch * (BH * BW)] = 0.0f;
        return;
    }

    const float* nb = g_norm + (size_t)b * BH * BW;
    const float EPS = 0.0001f;
#define NRM(a, c) nb[(a) * BW + (c)]
    float n1 = rsqrtf(NRM(i, j) + NRM(i + 1, j) + NRM(i, j + 1) + NRM(i + 1, j + 1) + EPS);
    float n2 = rsqrtf(NRM(i - 1, j) + NRM(i, j) + NRM(i - 1, j + 1) + NRM(i, j + 1) + EPS);
    float n3 = rsqrtf(NRM(i, j - 1) + NRM(i + 1, j - 1) + NRM(i, j) + NRM(i + 1, j) + EPS);
    float n4 = rsqrtf(NRM(i - 1, j - 1) + NRM(i, j - 1) + NRM(i - 1, j) + NRM(i, j) + EPS);
#undef NRM

    const float* hb = g_hist + (size_t)b * 18 * BH * BW + i * BW + j;

    float src[18];
#pragma unroll
    for (int o = 0; o < 18; o++) src[o] = hb[o * (BH * BW)];

    float t1 = 0.f, t2 = 0.f, t3 = 0.f, t4 = 0.f;
#pragma unroll
    for (int o = 0; o < 18; o++) {
        float h1 = fminf(src[o] * n1, 0.2f);
        float h2 = fminf(src[o] * n2, 0.2f);
        float h3 = fminf(src[o] * n3, 0.2f);
        float h4 = fminf(src[o] * n4, 0.2f);
        t1 += h1; t2 += h2; t3 += h3; t4 += h4;
        ob[o * (BH * BW)] = 0.5f * (h1 + h2 + h3 + h4);
    }
#pragma unroll
    for (int o = 0; o < 9; o++) {
        float ss = src[o] + src[o + 9];
        float v = fminf(ss * n1, 0.2f) + fminf(ss * n2, 0.2f) +
                  fminf(ss * n3, 0.2f) + fminf(ss * n4, 0.2f);
        ob[(18 + o) * (BH * BW)] = 0.5f * v;
    }
    ob[27 * (BH * BW)] = 0.2357f * t1;
    ob[28 * (BH * BW)] = 0.2357f * t2;
    ob[29 * (BH * BW)] = 0.2357f * t3;
    ob[30 * (BH * BW)] = 0.2357f * t4;
}

// ---------------------------------------------------------------------------
extern "C" void kernel_launch(void* const* d_in, const int* in_sizes, int n_in,
                              void* d_out, int out_size) {
    const float* img = (const float*)d_in[0];
    float* out = (float*)d_out;

    hog_grad<<<BATCH * IH * 128 / 256, 256>>>(img);   // 4096 blocks

    dim3 gcell(BW / 16 / 1, BH / 16, BATCH);          // (8, 8, 16)
    hog_cell<<<dim3(8, 8, BATCH), 256>>>();

    int n = BATCH * BH * BW;
    hog_feat<<<(n + 255) / 256, 256>>>(out);
}